// round 8
// baseline (speedup 1.0000x reference)
#include <cuda_runtime.h>
#include <cuda_fp16.h>
#include <cstdint>

// ---------------------------------------------------------------------------
// GaborSelfAttention as ONE 2-D-windowed fp16 HMMA GEMM:
//   out[ij,(b,f)] = sum_{h,kl} P[ij, h*1024+kl] * Y[(h,kl),(b,f)]
//   Y[(h,kl),(b,f)] = sum_e X[b,kl,e] * fc_w[f, e*8+h]   (fp16 HMMA, fp32 acc)
// M-tiles = (i-group of 4) x (j-group of 8) = 32 rows; K-support per tile is a
// uniform rectangle 12 k x 16 l x 8 heads = 1536 columns.
// ---------------------------------------------------------------------------

__device__ float  g_tab[8][420];            // exa[23] @0, eyb[63] @23, exy[331] @86
__device__ __half g_W2h[8 * 64 * 64];       // W2t[h][f][e]
__device__ __half g_Xh[32 * 1024 * 64];     // X fp16 [b][kl][e]        4 MB
__device__ __half g_A[1024 * 8192];         // P  [ij][h*1024+kl]      (windowed valid)
__device__ __half g_B[2048 * 8192];         // Y^T[b*64+f][h*1024+kl]  32 MB

// ------------------------------ PTX helpers -------------------------------
__device__ __forceinline__ uint32_t s2u(const void* p) {
    uint32_t a;
    asm("{ .reg .u64 t; cvta.to.shared.u64 t, %1; cvt.u32.u64 %0, t; }"
        : "=r"(a) : "l"(p));
    return a;
}
__device__ __forceinline__ void cpa16(uint32_t dst, const void* src) {
    asm volatile("cp.async.cg.shared.global [%0], [%1], 16;" :: "r"(dst), "l"(src));
}
__device__ __forceinline__ void cpa8(uint32_t dst, const void* src) {
    asm volatile("cp.async.ca.shared.global [%0], [%1], 8;" :: "r"(dst), "l"(src));
}
__device__ __forceinline__ void cpa_commit() {
    asm volatile("cp.async.commit_group;" ::: "memory");
}
template <int N> __device__ __forceinline__ void cpa_wait() {
    asm volatile("cp.async.wait_group %0;" :: "n"(N) : "memory");
}
__device__ __forceinline__ void mma16816(float c[4], const uint32_t a[4],
                                         const uint32_t b[2]) {
    asm volatile(
        "mma.sync.aligned.m16n8k16.row.col.f32.f16.f16.f32 "
        "{%0,%1,%2,%3}, {%4,%5,%6,%7}, {%8,%9}, {%0,%1,%2,%3};"
        : "+f"(c[0]), "+f"(c[1]), "+f"(c[2]), "+f"(c[3])
        : "r"(a[0]), "r"(a[1]), "r"(a[2]), "r"(a[3]), "r"(b[0]), "r"(b[1]));
}
__device__ __forceinline__ void ldm4(uint32_t r[4], uint32_t a) {
    asm volatile("ldmatrix.sync.aligned.m8n8.x4.shared.b16 {%0,%1,%2,%3}, [%4];"
        : "=r"(r[0]), "=r"(r[1]), "=r"(r[2]), "=r"(r[3]) : "r"(a));
}
__device__ __forceinline__ uint32_t swz(uint32_t o) { return o ^ ((o >> 3) & 0x70); }

// ------------------------------ small kernels -----------------------------
// tables: exa[dx+11] |dx|<=11, eyb[dy+31] |dy|<=31, exy[m+165] |m|<=165
__global__ void k_tab(const float* __restrict__ centers,
                      const float* __restrict__ spreads) {
    const int h = blockIdx.x;
    float s00 = spreads[h*4+0], s01 = spreads[h*4+1];
    float s10 = spreads[h*4+2], s11 = spreads[h*4+3];
    float a  = s00*s00 + s01*s01;
    float bb = s00*s10 + s01*s11;
    float c  = s10*s10 + s11*s11;
    float m1 = centers[h*2+0], m2 = centers[h*2+1];
    float u0 = a*m1 + bb*m2;
    float u1 = c*m2 + bb*m1;
    float u2 = -0.5f*a;
    float u3 = -0.5f*c;
    float u4 = -bb;
    for (int t = threadIdx.x; t < 417; t += 256) {
        float v;
        if (t < 23)      { float dx = (float)(t - 11);       v = expf((u0 + u2*dx)*dx); }
        else if (t < 86) { float dy = (float)(t - 23 - 31);  v = expf((u1 + u3*dy)*dy); }
        else             { float m  = (float)(t - 86 - 165); v = expf(u4*m); }
        g_tab[h][t] = v;
    }
}

// W2t[h][f][e] = fc_w[f*512 + e*8 + h]  (fp16)
__global__ void k_w2h(const float* __restrict__ fc_w) {
    int idx = blockIdx.x * 256 + threadIdx.x;    // 32768
    int h = idx >> 12, f = (idx >> 6) & 63, e = idx & 63;
    g_W2h[idx] = __float2half_rn(fc_w[f*512 + e*8 + h]);
}

// X -> fp16 (layout unchanged)
__global__ void k_xh(const float* __restrict__ X) {
    int i = blockIdx.x * 256 + threadIdx.x;      // 262144, 8 floats each
    const float4* src = (const float4*)X + (size_t)i * 2;
    float4 v0 = src[0], v1 = src[1];
    __half2 a = __floats2half2_rn(v0.x, v0.y);
    __half2 b = __floats2half2_rn(v0.z, v0.w);
    __half2 c = __floats2half2_rn(v1.x, v1.y);
    __half2 d = __floats2half2_rn(v1.z, v1.w);
    *(uint4*)&g_Xh[(size_t)i * 8] =
        make_uint4(*(uint32_t*)&a, *(uint32_t*)&b, *(uint32_t*)&c, *(uint32_t*)&d);
}

// ---------------------------------------------------------------------------
// Y^T via HMMA: block per (b, h, half): 4 pipelined chunks of 128 kl.
// [128 kl x 64 e] @ [64 e x 64 f] per chunk; transpose epilogue -> Y^T.
// dyn smem: W 8K @0 | X0 16K @8192 | X1 16K @24576 | T 17.4K @40960 = 58368 B
// ---------------------------------------------------------------------------
#define Y2_SMEM 58368
__global__ __launch_bounds__(256) void k_y2() {
    extern __shared__ __align__(1024) char dsm[];
    const uint32_t sb = s2u(dsm);
    __half* T = (__half*)(dsm + 40960);
    const int tid = threadIdx.x, l = tid & 31, wid = tid >> 5;
    const int bx = blockIdx.x;               // 0..511
    const int b = bx >> 4, h = (bx >> 1) & 7, half = bx & 1;

    auto loadX = [&](int c) {
        uint32_t xs = sb + 8192 + (c & 1) * 16384;
        const __half* Xg = g_Xh + ((size_t)b*1024 + half*512 + c*128) * 64;
#pragma unroll
        for (int q = 0; q < 4; q++) {
            int idx = q*256 + tid;
            int r = idx >> 3, cc = idx & 7;
            cpa16(xs + swz(r*128 + cc*16), Xg + (size_t)r*64 + cc*8);
        }
        cpa_commit();
    };

    // group 0: W + X0
    {
        const __half* Wg = g_W2h + h*4096;
#pragma unroll
        for (int q = 0; q < 2; q++) {
            int idx = q*256 + tid;
            int r = idx >> 3, cc = idx & 7;
            cpa16(sb + swz(r*128 + cc*16), Wg + (size_t)r*64 + cc*8);
        }
        loadX(0);      // commits W + X0 as one group
    }
    loadX(1);

    const int lm_r = (l & 7) + ((l >> 3) & 1) * 8;
    const int lm_c = l >> 4;
    const int r8 = l >> 2, kq = (l & 3) * 2;

    for (int c = 0; c < 4; c++) {
        if (c < 3) cpa_wait<1>(); else cpa_wait<0>();
        __syncthreads();

        const uint32_t xs = sb + 8192 + (c & 1) * 16384;
        float acc[8][4];
#pragma unroll
        for (int ni = 0; ni < 8; ni++)
#pragma unroll
            for (int q = 0; q < 4; q++) acc[ni][q] = 0.f;

#pragma unroll
        for (int ks = 0; ks < 4; ks++) {
            const int ch = 2*ks + lm_c;
            uint32_t a[4], bq[4][4];
            ldm4(a, xs + swz((wid*16 + lm_r)*128 + ch*16));
#pragma unroll
            for (int nb = 0; nb < 4; nb++)
                ldm4(bq[nb], sb + swz((nb*16 + lm_r)*128 + ch*16));
#pragma unroll
            for (int ni = 0; ni < 8; ni++) {
                uint32_t bb[2] = {bq[ni>>1][ni&1], bq[ni>>1][(ni&1)+2]};
                mma16816(acc[ni], a, bb);
            }
        }
        __syncthreads();                 // all reads of stage done
        if (c + 2 < 4) loadX(c + 2);

        // transpose: T[f][kl] stride 136
#pragma unroll
        for (int ni = 0; ni < 8; ni++) {
            int m0 = wid*16 + r8;
            int n0 = ni*8 + kq;
            T[n0*136 + m0]         = __float2half_rn(acc[ni][0]);
            T[(n0+1)*136 + m0]     = __float2half_rn(acc[ni][1]);
            T[n0*136 + m0 + 8]     = __float2half_rn(acc[ni][2]);
            T[(n0+1)*136 + m0 + 8] = __float2half_rn(acc[ni][3]);
        }
        __syncthreads();
#pragma unroll
        for (int q = 0; q < 4; q++) {
            int idx = q*256 + tid;
            int f = idx >> 4, mc = idx & 15;
            uint4 v = *(const uint4*)&T[f*136 + mc*8];
            *(uint4*)&g_B[((size_t)b*64 + f)*8192 + h*1024 + half*512 + c*128 + mc*8] = v;
        }
        __syncthreads();                 // T reusable
    }
}

// ---------------------------------------------------------------------------
// P on the rectangular support: per (ij,h): k in [kg0,kg0+12), l in [lg0,lg0+16)
// kg0 = clamp((i&~3)-4, 0, 20), lg0 = clamp((j&~7)-4, 0, 16).
// grid = 1024 (ij), 8 warps = 8 heads, 192 values per warp (6 per lane).
// ---------------------------------------------------------------------------
__global__ __launch_bounds__(256) void k_probs() {
    __shared__ float tab[8][420];
    const int tid = threadIdx.x, l = tid & 31, wid = tid >> 5;
#pragma unroll
    for (int q = 0; q < 14; q++) {
        int idx = q*256 + tid;            // 3360 floats
        if (idx < 3360) ((float*)tab)[idx] = ((const float*)g_tab)[idx];
    }
    __syncthreads();

    const int ij = blockIdx.x;
    const int i = ij >> 5, j = ij & 31;
    const int kg0 = min(max((i & ~3) - 4, 0), 20);
    const int lg0 = min(max((j & ~7) - 4, 0), 16);
    const float* th = tab[wid];

    float vals[6];
    float s = 0.f;
#pragma unroll
    for (int t = 0; t < 6; t++) {
        int pos = t*32 + l;              // 0..191
        int kk = pos >> 4, ll = pos & 15;
        int dx = kg0 + kk - i;
        int dy = lg0 + ll - j;
        float p = th[dx + 11] * th[23 + dy + 31] * th[86 + dx*dy + 165];
        vals[t] = p;
        s += p;
    }
#pragma unroll
    for (int o = 16; o > 0; o >>= 1) s += __shfl_xor_sync(0xffffffffu, s, o);
    const float inv = 1.0f / s;

    __half* out = g_A + (size_t)ij*8192 + wid*1024;
#pragma unroll
    for (int t = 0; t < 6; t++) {
        int pos = t*32 + l;
        int kk = pos >> 4, ll = pos & 15;
        out[(kg0 + kk)*32 + lg0 + ll] = __float2half_rn(vals[t] * inv);
    }
}

// ---------------------------------------------------------------------------
// Main GEMM: BM=32 (4i x 8j), BN=128, uniform K = 8h x 12k x 16l = 1536.
// 24 stages of 64 cols (1 h, 4 k, 16 l).  256 threads (2x4 warps), 4 stages.
// stage smem: A 4KB + B 16KB = 20KB; 4 stages = 80KB dynamic.
// lg0 in {4,12} makes global sources only 8B-aligned -> 8B cp.async path.
// ---------------------------------------------------------------------------
#define GSTG 20480
__global__ __launch_bounds__(256, 1) void k_gemm(const float* __restrict__ fc_b,
                                                 float* __restrict__ out) {
    extern __shared__ __align__(1024) char sm[];
    const uint32_t sbase = s2u(sm);
    const int tid = threadIdx.x, l = tid & 31, wid = tid >> 5;
    const int warp_m = wid >> 2, warp_n = wid & 3;
    const int bn = blockIdx.x, bm = blockIdx.y;

    const int i0 = (bm >> 2) * 4, j0 = (bm & 3) * 8;
    const int kg0 = min(max(i0 - 4, 0), 20);
    const int lg0 = min(max(j0 - 4, 0), 16);
    const bool al16 = ((lg0 & 7) == 0);
    const int nt = 24;

    // per-thread A source row (fixed): r = tid>>3 -> ij row
    const int ar = tid >> 3, ac = tid & 7;
    const size_t arow_off = (size_t)((i0 + (ar >> 3)) * 32 + j0 + (ar & 7)) * 8192;

    auto load_stage = [&](int buf, int s) {
        const int hh = s / 3, k3 = s - hh * 3;
        const int colbase = hh*1024 + (kg0 + k3*4)*32 + lg0;
        uint32_t Ab = sbase + buf*GSTG, Bb = Ab + 4096;
        const __half* Asrc = g_A + arow_off + colbase + (ac >> 1)*32 + (ac & 1)*8;
        const uint32_t Adst = Ab + swz(ar*128 + ac*16);
        const __half* Bg = g_B + (size_t)(bn*128)*8192 + colbase;
        if (al16) {
            cpa16(Adst, Asrc);
#pragma unroll
            for (int q = 0; q < 4; q++) {
                int idx = q*256 + tid;
                int r = idx >> 3, c = idx & 7;
                cpa16(Bb + swz(r*128 + c*16),
                      Bg + (size_t)r*8192 + (c >> 1)*32 + (c & 1)*8);
            }
        } else {
            cpa8(Adst, Asrc);
            cpa8(Adst + 8, Asrc + 4);
#pragma unroll
            for (int q = 0; q < 4; q++) {
                int idx = q*256 + tid;
                int r = idx >> 3, c = idx & 7;
                const __half* src = Bg + (size_t)r*8192 + (c >> 1)*32 + (c & 1)*8;
                uint32_t dst = Bb + swz(r*128 + c*16);
                cpa8(dst, src);
                cpa8(dst + 8, src + 4);
            }
        }
        cpa_commit();
    };

    float acc[4][4];
#pragma unroll
    for (int ni = 0; ni < 4; ni++)
#pragma unroll
        for (int q = 0; q < 4; q++) acc[ni][q] = 0.f;

    load_stage(0, 0); load_stage(1, 1); load_stage(2, 2);

    const int lm_r = (l & 7) + ((l >> 3) & 1) * 8;
    const int lm_c = l >> 4;

    for (int t = 0; t < nt; t++) {
        __syncthreads();
        if (t + 3 < nt) { load_stage((t+3)&3, t+3); cpa_wait<3>(); }
        else if (t + 2 < nt) cpa_wait<2>();
        else if (t + 1 < nt) cpa_wait<1>();
        else                 cpa_wait<0>();
        __syncthreads();

        const uint32_t Ab = sbase + (t&3)*GSTG, Bb = Ab + 4096;
#pragma unroll
        for (int ks = 0; ks < 4; ks++) {
            const int ch = 2*ks + lm_c;
            uint32_t a[4], bq[2][4];
            ldm4(a, Ab + swz((warp_m*16 + lm_r)*128 + ch*16));
#pragma unroll
            for (int nb = 0; nb < 2; nb++)
                ldm4(bq[nb], Bb + swz((warp_n*32 + nb*16 + lm_r)*128 + ch*16));
#pragma unroll
            for (int ni = 0; ni < 4; ni++) {
                uint32_t bb[2] = {bq[ni>>1][ni&1], bq[ni>>1][(ni&1)+2]};
                mma16816(acc[ni], a, bb);
            }
        }
    }

    // epilogue
    const int r8 = l >> 2, kq = (l & 3) * 2;
    const int fbase = (warp_n & 1) * 32 + kq;
    const int bidx = bn * 2 + (warp_n >> 1);
    const int m0 = warp_m*16 + r8;
    const int ij0 = (i0 + (m0 >> 3))*32 + j0 + (m0 & 7);   // second row: ij0+32
    float2 bias[4];
#pragma unroll
    for (int ni = 0; ni < 4; ni++)
        bias[ni] = make_float2(fc_b[fbase + ni*8], fc_b[fbase + ni*8 + 1]);

    float* outb = out + (size_t)bidx * 65536;
#pragma unroll
    for (int ni = 0; ni < 4; ni++) {
        int f = fbase + ni*8;
        *(float2*)&outb[(size_t)ij0 * 64 + f] =
            make_float2(acc[ni][0] + bias[ni].x, acc[ni][1] + bias[ni].y);
        *(float2*)&outb[(size_t)(ij0 + 32) * 64 + f] =
            make_float2(acc[ni][2] + bias[ni].x, acc[ni][3] + bias[ni].y);
    }
}

// ---------------------------------------------------------------------------
extern "C" void kernel_launch(void* const* d_in, const int* in_sizes, int n_in,
                              void* d_out, int out_size) {
    const float* X       = (const float*)d_in[0];
    const float* centers = (const float*)d_in[2];
    const float* spreads = (const float*)d_in[3];
    const float* fc_w    = (const float*)d_in[4];
    const float* fc_b    = (const float*)d_in[5];
    float* out = (float*)d_out;

    cudaFuncSetAttribute(k_y2, cudaFuncAttributeMaxDynamicSharedMemorySize, Y2_SMEM);
    cudaFuncSetAttribute(k_gemm, cudaFuncAttributeMaxDynamicSharedMemorySize, 4*GSTG);

    k_tab<<<8, 256>>>(centers, spreads);
    k_w2h<<<128, 256>>>(fc_w);
    k_xh<<<1024, 256>>>(X);
    k_y2<<<512, 256, Y2_SMEM>>>();
    k_probs<<<1024, 256>>>();
    dim3 gg(16, 32);
    k_gemm<<<gg, 256, 4*GSTG>>>(fc_b, out);
}